// round 1
// baseline (speedup 1.0000x reference)
#include <cuda_runtime.h>
#include <math.h>

#define NUM_BLOCKS 1184
#define NUM_THREADS 256

__device__ float g_partials[NUM_BLOCKS];

__global__ __launch_bounds__(NUM_THREADS)
void sqdiff_reduce_kernel(const float* __restrict__ o,
                          const float* __restrict__ x,
                          long long n4)
{
    const float4* __restrict__ o4 = (const float4*)o;
    const float4* __restrict__ x4 = (const float4*)x;

    float acc = 0.0f;
    long long stride = (long long)gridDim.x * blockDim.x;
    long long i = (long long)blockIdx.x * blockDim.x + threadIdx.x;

    // 2-deep unrolled grid-stride loop for MLP (8 outstanding 16B loads)
    for (; i + stride < n4; i += 2 * stride) {
        float4 a0 = o4[i];
        float4 b0 = x4[i];
        float4 a1 = o4[i + stride];
        float4 b1 = x4[i + stride];
        float d0 = a0.x - b0.x, d1 = a0.y - b0.y, d2 = a0.z - b0.z, d3 = a0.w - b0.w;
        float e0 = a1.x - b1.x, e1 = a1.y - b1.y, e2 = a1.z - b1.z, e3 = a1.w - b1.w;
        acc = fmaf(d0, d0, acc); acc = fmaf(d1, d1, acc);
        acc = fmaf(d2, d2, acc); acc = fmaf(d3, d3, acc);
        acc = fmaf(e0, e0, acc); acc = fmaf(e1, e1, acc);
        acc = fmaf(e2, e2, acc); acc = fmaf(e3, e3, acc);
    }
    for (; i < n4; i += stride) {
        float4 a = o4[i];
        float4 b = x4[i];
        float d0 = a.x - b.x, d1 = a.y - b.y, d2 = a.z - b.z, d3 = a.w - b.w;
        acc = fmaf(d0, d0, acc); acc = fmaf(d1, d1, acc);
        acc = fmaf(d2, d2, acc); acc = fmaf(d3, d3, acc);
    }

    // warp reduce
    #pragma unroll
    for (int off = 16; off > 0; off >>= 1)
        acc += __shfl_xor_sync(0xFFFFFFFFu, acc, off);

    __shared__ float warp_sums[NUM_THREADS / 32];
    int lane = threadIdx.x & 31;
    int wid  = threadIdx.x >> 5;
    if (lane == 0) warp_sums[wid] = acc;
    __syncthreads();

    if (wid == 0) {
        float v = (lane < NUM_THREADS / 32) ? warp_sums[lane] : 0.0f;
        #pragma unroll
        for (int off = 4; off > 0; off >>= 1)
            v += __shfl_xor_sync(0xFFFFFFFFu, v, off);
        if (lane == 0) g_partials[blockIdx.x] = v;
    }
}

__global__ __launch_bounds__(1024)
void finalize_kernel(const float* __restrict__ noise_p,
                     float* __restrict__ out,
                     double nd)
{
    __shared__ double s_sums[32];
    double s = 0.0;
    for (int i = threadIdx.x; i < NUM_BLOCKS; i += blockDim.x)
        s += (double)g_partials[i];

    // warp reduce in double
    #pragma unroll
    for (int off = 16; off > 0; off >>= 1)
        s += __shfl_xor_sync(0xFFFFFFFFu, s, off);

    int lane = threadIdx.x & 31;
    int wid  = threadIdx.x >> 5;
    if (lane == 0) s_sums[wid] = s;
    __syncthreads();

    if (wid == 0) {
        double v = (lane < 32) ? s_sums[lane] : 0.0;
        #pragma unroll
        for (int off = 16; off > 0; off >>= 1)
            v += __shfl_xor_sync(0xFFFFFFFFu, v, off);
        if (lane == 0) {
            const double LOG_2PI = 1.8378770664093453;
            double noise = (double)noise_p[0];
            double result = -0.5 * nd * LOG_2PI
                          - 0.5 * nd * noise
                          - 0.5 * exp(-2.0 * noise) * v;
            out[0] = (float)result;
        }
    }
}

extern "C" void kernel_launch(void* const* d_in, const int* in_sizes, int n_in,
                              void* d_out, int out_size)
{
    const float* o     = (const float*)d_in[0];
    const float* x     = (const float*)d_in[1];
    const float* noise = (const float*)d_in[2];
    float* out = (float*)d_out;

    long long n  = (long long)in_sizes[0];   // total elements in o
    long long n4 = n >> 2;                   // float4 count (n divisible by 4)

    sqdiff_reduce_kernel<<<NUM_BLOCKS, NUM_THREADS>>>(o, x, n4);
    finalize_kernel<<<1, 1024>>>(noise, out, (double)n);
}